// round 4
// baseline (speedup 1.0000x reference)
#include <cuda_runtime.h>
#include <cuda_bf16.h>
#include <math_constants.h>

// Problem constants (fixed by the dataset)
#define BQ      1024       // queries
#define DD      128        // dim
#define TOPK    8
#define NCHUNKS 74         // key chunks (grid.x) -> 74*8 = 592 CTAs = 4 full waves
#define QT      128        // queries per CTA
#define KT      64         // keys per tile
#define SMP     65         // sims row pitch (bank-conflict-free scan)

// Scratch (no cudaMalloc allowed)
__device__ float g_qn[BQ * DD];                    // normalized queries
__device__ float g_rk[500032];                     // 1/||k||
__device__ float g_cs[BQ * NCHUNKS * TOPK];        // per-chunk candidate scores
__device__ int   g_ci[BQ * NCHUNKS * TOPK];        // per-chunk candidate indices

// ---------------- query normalization ----------------
__global__ void normq_kernel(const float* __restrict__ q) {
    int b = blockIdx.x;
    int t = threadIdx.x;                 // 128 threads, one per dim
    float v = q[b * DD + t];
    float s = v * v;
    #pragma unroll
    for (int off = 16; off; off >>= 1) s += __shfl_xor_sync(0xffffffff, s, off);
    __shared__ float ws[4];
    if ((t & 31) == 0) ws[t >> 5] = s;
    __syncthreads();
    float tot = ws[0] + ws[1] + ws[2] + ws[3];
    float inv = 1.0f / fmaxf(sqrtf(tot), 1e-12f);
    g_qn[b * DD + t] = v * inv;
}

// ---------------- key reciprocal norms ----------------
__global__ void rnormk_kernel(const float* __restrict__ keys, int N) {
    int gw = (blockIdx.x * blockDim.x + threadIdx.x) >> 5;  // one warp per key row
    int lane = threadIdx.x & 31;
    if (gw >= N) return;
    float4 v = *(const float4*)(keys + (size_t)gw * DD + lane * 4);
    float s = v.x * v.x + v.y * v.y + v.z * v.z + v.w * v.w;
    #pragma unroll
    for (int off = 16; off; off >>= 1) s += __shfl_xor_sync(0xffffffff, s, off);
    if (lane == 0) g_rk[gw] = 1.0f / fmaxf(sqrtf(s), 1e-12f);
}

// sorted-descending branch-free top-8 insert (register resident, fully unrolled)
__device__ __forceinline__ void insert_top8(float (&ts)[TOPK], int (&ti)[TOPK],
                                            float s, int id) {
    #pragma unroll
    for (int j = TOPK - 1; j >= 1; j--) {
        if (ts[j] < s) {
            bool here = ts[j - 1] >= s;
            ts[j] = here ? s : ts[j - 1];
            ti[j] = here ? id : ti[j - 1];
        }
    }
    if (ts[0] < s) { ts[0] = s; ti[0] = id; }
}

// ---------------- fused sim-GEMM + per-chunk top-8 ----------------
// grid: (NCHUNKS, B/QT), block: 256
// smem: qs[128][128] d-major | ks[128][64] d-major | sm[128][65] | rks[64]
#define SH_QS 0
#define SH_KS 16384
#define SH_SM 24576
#define SH_RK (24576 + QT * SMP)
#define SMEM_FLOATS (SH_RK + KT)
#define SMEM_BYTES  (SMEM_FLOATS * 4)

__global__ void __launch_bounds__(256, 1)
simtopk_kernel(const float* __restrict__ keys, int N, int CH) {
    extern __shared__ float sh[];
    float* qs  = sh + SH_QS;
    float* ks  = sh + SH_KS;
    float* sm  = sh + SH_SM;
    float* rks = sh + SH_RK;

    const int tid = threadIdx.x;
    const int qBase = blockIdx.y * QT;
    const int c0 = blockIdx.x * CH;
    const int c1 = min(c0 + CH, N);

    // Load q tile transposed to d-major: qs[d][q]. Coalesced global float4.
    for (int i = tid; i < 32 * QT; i += 256) {
        int d4 = i >> 7;            // 0..31
        int q  = i & 127;
        float4 v = *(const float4*)(g_qn + (size_t)(qBase + q) * DD + d4 * 4);
        qs[(d4 * 4 + 0) * QT + q] = v.x;
        qs[(d4 * 4 + 1) * QT + q] = v.y;
        qs[(d4 * 4 + 2) * QT + q] = v.z;
        qs[(d4 * 4 + 3) * QT + q] = v.w;
    }

    const int tx = tid & 15;        // key group:   k = tx*4 + i
    const int ty = tid >> 4;        // query group: q = ty*8 + j

    float ts[TOPK];
    int   ti[TOPK];
    #pragma unroll
    for (int j = 0; j < TOPK; j++) { ts[j] = -CUDART_INF_F; ti[j] = 0; }

    __syncthreads();

    for (int n0 = c0; n0 < c1; n0 += KT) {
        const int kc = min(KT, c1 - n0);

        // Load key tile transposed to d-major: ks[d][k]. (bank-conflict-free stores)
        for (int i = tid; i < 32 * KT; i += 256) {
            int d4 = i >> 6;        // 0..31
            int k  = i & 63;
            float4 v = make_float4(0.f, 0.f, 0.f, 0.f);
            if (k < kc) v = *(const float4*)(keys + (size_t)(n0 + k) * DD + d4 * 4);
            ks[(d4 * 4 + 0) * KT + k] = v.x;
            ks[(d4 * 4 + 1) * KT + k] = v.y;
            ks[(d4 * 4 + 2) * KT + k] = v.z;
            ks[(d4 * 4 + 3) * KT + k] = v.w;
        }
        if (tid < KT) rks[tid] = (tid < kc) ? g_rk[n0 + tid] : 0.f;
        __syncthreads();   // A: ks/rks ready; prior-tile scan complete before sm rewrite

        // Register-tiled 128x64 fp32 GEMM over d=0..127
        float acc[8][4];
        #pragma unroll
        for (int j = 0; j < 8; j++)
            #pragma unroll
            for (int i = 0; i < 4; i++) acc[j][i] = 0.f;

        #pragma unroll 4
        for (int d = 0; d < DD; d++) {
            float4 bb = *(const float4*)(ks + d * KT + tx * 4);
            float4 a0 = *(const float4*)(qs + d * QT + ty * 8);
            float4 a1 = *(const float4*)(qs + d * QT + ty * 8 + 4);
            float av[8] = {a0.x, a0.y, a0.z, a0.w, a1.x, a1.y, a1.z, a1.w};
            #pragma unroll
            for (int j = 0; j < 8; j++) {
                acc[j][0] += av[j] * bb.x;
                acc[j][1] += av[j] * bb.y;
                acc[j][2] += av[j] * bb.z;
                acc[j][3] += av[j] * bb.w;
            }
        }

        // Scale by 1/||k|| and stage sims tile
        float4 rr = *(const float4*)(rks + tx * 4);
        float rv[4] = {rr.x, rr.y, rr.z, rr.w};
        #pragma unroll
        for (int j = 0; j < 8; j++)
            #pragma unroll
            for (int i = 0; i < 4; i++)
                sm[(ty * 8 + j) * SMP + tx * 4 + i] = acc[j][i] * rv[i];
        __syncthreads();   // B: sims visible; compute reads of ks done before next load

        // Per-query top-8 scan (threads 0..127, conflict-free via SMP=65)
        if (tid < QT) {
            const float* row = sm + tid * SMP;
            float mn = ts[TOPK - 1];
            for (int k = 0; k < kc; k++) {
                float s = row[k];
                if (s > mn) { insert_top8(ts, ti, s, n0 + k); mn = ts[TOPK - 1]; }
            }
        }
        // no barrier needed: next iteration's sync A orders scan before sm rewrite
    }

    if (tid < QT) {
        int q = qBase + tid;
        size_t base = ((size_t)q * NCHUNKS + blockIdx.x) * TOPK;
        #pragma unroll
        for (int j = 0; j < TOPK; j++) { g_cs[base + j] = ts[j]; g_ci[base + j] = ti[j]; }
    }
}

// ---------------- merge per-chunk candidates + gather values ----------------
__global__ void merge_gather_kernel(const float* __restrict__ values,
                                    float* __restrict__ out) {
    const int q = blockIdx.x;
    const int tid = threadIdx.x;
    const int TOT = NCHUNKS * TOPK;    // 592
    __shared__ float cs[NCHUNKS * TOPK];
    __shared__ int   ci[NCHUNKS * TOPK];
    __shared__ int   sel[TOPK];

    for (int i = tid; i < TOT; i += 256) {
        cs[i] = g_cs[(size_t)q * TOT + i];
        ci[i] = g_ci[(size_t)q * TOT + i];
    }
    __syncthreads();

    if (tid < 32) {
        for (int r = 0; r < TOPK; r++) {
            float bs = -CUDART_INF_F; int bi = 0x7fffffff; int bj = 0;
            for (int i = tid; i < TOT; i += 32) {
                float s = cs[i]; int ix = ci[i];
                if (s > bs || (s == bs && ix < bi)) { bs = s; bi = ix; bj = i; }
            }
            #pragma unroll
            for (int off = 16; off; off >>= 1) {
                float os = __shfl_xor_sync(0xffffffff, bs, off);
                int   oi = __shfl_xor_sync(0xffffffff, bi, off);
                int   oj = __shfl_xor_sync(0xffffffff, bj, off);
                if (os > bs || (os == bs && oi < bi)) { bs = os; bi = oi; bj = oj; }
            }
            if (tid == 0) { sel[r] = bi; cs[bj] = -CUDART_INF_F; }
            __syncwarp();
        }
    }
    __syncthreads();

    for (int i = tid; i < TOPK * DD; i += 256) {
        int r = i >> 7, d = i & 127;
        out[((size_t)q * TOPK + r) * DD + d] = values[(size_t)sel[r] * DD + d];
    }
}

// ---------------- launch ----------------
extern "C" void kernel_launch(void* const* d_in, const int* in_sizes, int n_in,
                              void* d_out, int out_size) {
    const float* q_emb = (const float*)d_in[0];
    const float* keys  = (const float*)d_in[1];
    const float* vals  = (const float*)d_in[2];
    float* out = (float*)d_out;

    int B = in_sizes[0] / DD;        // 1024
    int N = in_sizes[1] / DD;        // 500000
    int CH = (N + NCHUNKS - 1) / NCHUNKS;

    normq_kernel<<<B, 128>>>(q_emb);
    rnormk_kernel<<<(N + 7) / 8, 256>>>(keys, N);

    cudaFuncSetAttribute(simtopk_kernel,
                         cudaFuncAttributeMaxDynamicSharedMemorySize, SMEM_BYTES);
    dim3 grid(NCHUNKS, B / QT);
    simtopk_kernel<<<grid, 256, SMEM_BYTES>>>(keys, N, CH);

    merge_gather_kernel<<<B, 256>>>(vals, out);
}

// round 5
// speedup vs baseline: 1.0011x; 1.0011x over previous
#include <cuda_runtime.h>
#include <cuda_bf16.h>
#include <math_constants.h>

// Problem constants (fixed by the dataset)
#define BQ      1024       // queries
#define DD      128        // dim
#define TOPK    8
#define NCHUNKS 74         // key chunks (grid.x) -> 74*8 = 592 CTAs = 4 full waves
#define QT      128        // queries per CTA
#define KT      64         // keys per tile
#define SMP     65         // sims row pitch (bank-conflict-free scan)

// Scratch (no cudaMalloc allowed)
__device__ float g_qn[BQ * DD];                    // normalized queries
__device__ float g_rk[500032];                     // 1/||k||
__device__ float g_cs[BQ * NCHUNKS * TOPK];        // per-chunk candidate scores
__device__ int   g_ci[BQ * NCHUNKS * TOPK];        // per-chunk candidate indices

// ---------------- query normalization ----------------
__global__ void normq_kernel(const float* __restrict__ q) {
    int b = blockIdx.x;
    int t = threadIdx.x;                 // 128 threads, one per dim
    float v = q[b * DD + t];
    float s = v * v;
    #pragma unroll
    for (int off = 16; off; off >>= 1) s += __shfl_xor_sync(0xffffffff, s, off);
    __shared__ float ws[4];
    if ((t & 31) == 0) ws[t >> 5] = s;
    __syncthreads();
    float tot = ws[0] + ws[1] + ws[2] + ws[3];
    float inv = 1.0f / fmaxf(sqrtf(tot), 1e-12f);
    g_qn[b * DD + t] = v * inv;
}

// ---------------- key reciprocal norms ----------------
__global__ void rnormk_kernel(const float* __restrict__ keys, int N) {
    int gw = (blockIdx.x * blockDim.x + threadIdx.x) >> 5;  // one warp per key row
    int lane = threadIdx.x & 31;
    if (gw >= N) return;
    float4 v = *(const float4*)(keys + (size_t)gw * DD + lane * 4);
    float s = v.x * v.x + v.y * v.y + v.z * v.z + v.w * v.w;
    #pragma unroll
    for (int off = 16; off; off >>= 1) s += __shfl_xor_sync(0xffffffff, s, off);
    if (lane == 0) g_rk[gw] = 1.0f / fmaxf(sqrtf(s), 1e-12f);
}

// sorted-descending branch-free top-8 insert (register resident, fully unrolled)
__device__ __forceinline__ void insert_top8(float (&ts)[TOPK], int (&ti)[TOPK],
                                            float s, int id) {
    #pragma unroll
    for (int j = TOPK - 1; j >= 1; j--) {
        if (ts[j] < s) {
            bool here = ts[j - 1] >= s;
            ts[j] = here ? s : ts[j - 1];
            ti[j] = here ? id : ti[j - 1];
        }
    }
    if (ts[0] < s) { ts[0] = s; ti[0] = id; }
}

// ---------------- fused sim-GEMM + per-chunk top-8 ----------------
// grid: (NCHUNKS, B/QT), block: 256
// smem: qs[128][128] d-major | ks[128][64] d-major | sm[128][65] | rks[64]
#define SH_QS 0
#define SH_KS 16384
#define SH_SM 24576
#define SH_RK (24576 + QT * SMP)
#define SMEM_FLOATS (SH_RK + KT)
#define SMEM_BYTES  (SMEM_FLOATS * 4)

__global__ void __launch_bounds__(256, 1)
simtopk_kernel(const float* __restrict__ keys, int N, int CH) {
    extern __shared__ float sh[];
    float* qs  = sh + SH_QS;
    float* ks  = sh + SH_KS;
    float* sm  = sh + SH_SM;
    float* rks = sh + SH_RK;

    const int tid = threadIdx.x;
    const int qBase = blockIdx.y * QT;
    const int c0 = blockIdx.x * CH;
    const int c1 = min(c0 + CH, N);

    // Load q tile transposed to d-major: qs[d][q]. Coalesced global float4.
    for (int i = tid; i < 32 * QT; i += 256) {
        int d4 = i >> 7;            // 0..31
        int q  = i & 127;
        float4 v = *(const float4*)(g_qn + (size_t)(qBase + q) * DD + d4 * 4);
        qs[(d4 * 4 + 0) * QT + q] = v.x;
        qs[(d4 * 4 + 1) * QT + q] = v.y;
        qs[(d4 * 4 + 2) * QT + q] = v.z;
        qs[(d4 * 4 + 3) * QT + q] = v.w;
    }

    const int tx = tid & 15;        // key group:   k = tx*4 + i
    const int ty = tid >> 4;        // query group: q = ty*8 + j

    float ts[TOPK];
    int   ti[TOPK];
    #pragma unroll
    for (int j = 0; j < TOPK; j++) { ts[j] = -CUDART_INF_F; ti[j] = 0; }

    __syncthreads();

    for (int n0 = c0; n0 < c1; n0 += KT) {
        const int kc = min(KT, c1 - n0);

        // Load key tile transposed to d-major: ks[d][k]. (bank-conflict-free stores)
        for (int i = tid; i < 32 * KT; i += 256) {
            int d4 = i >> 6;        // 0..31
            int k  = i & 63;
            float4 v = make_float4(0.f, 0.f, 0.f, 0.f);
            if (k < kc) v = *(const float4*)(keys + (size_t)(n0 + k) * DD + d4 * 4);
            ks[(d4 * 4 + 0) * KT + k] = v.x;
            ks[(d4 * 4 + 1) * KT + k] = v.y;
            ks[(d4 * 4 + 2) * KT + k] = v.z;
            ks[(d4 * 4 + 3) * KT + k] = v.w;
        }
        if (tid < KT) rks[tid] = (tid < kc) ? g_rk[n0 + tid] : 0.f;
        __syncthreads();   // A: ks/rks ready; prior-tile scan complete before sm rewrite

        // Register-tiled 128x64 fp32 GEMM over d=0..127
        float acc[8][4];
        #pragma unroll
        for (int j = 0; j < 8; j++)
            #pragma unroll
            for (int i = 0; i < 4; i++) acc[j][i] = 0.f;

        #pragma unroll 4
        for (int d = 0; d < DD; d++) {
            float4 bb = *(const float4*)(ks + d * KT + tx * 4);
            float4 a0 = *(const float4*)(qs + d * QT + ty * 8);
            float4 a1 = *(const float4*)(qs + d * QT + ty * 8 + 4);
            float av[8] = {a0.x, a0.y, a0.z, a0.w, a1.x, a1.y, a1.z, a1.w};
            #pragma unroll
            for (int j = 0; j < 8; j++) {
                acc[j][0] += av[j] * bb.x;
                acc[j][1] += av[j] * bb.y;
                acc[j][2] += av[j] * bb.z;
                acc[j][3] += av[j] * bb.w;
            }
        }

        // Scale by 1/||k|| and stage sims tile
        float4 rr = *(const float4*)(rks + tx * 4);
        float rv[4] = {rr.x, rr.y, rr.z, rr.w};
        #pragma unroll
        for (int j = 0; j < 8; j++)
            #pragma unroll
            for (int i = 0; i < 4; i++)
                sm[(ty * 8 + j) * SMP + tx * 4 + i] = acc[j][i] * rv[i];
        __syncthreads();   // B: sims visible; compute reads of ks done before next load

        // Per-query top-8 scan (threads 0..127, conflict-free via SMP=65)
        if (tid < QT) {
            const float* row = sm + tid * SMP;
            float mn = ts[TOPK - 1];
            for (int k = 0; k < kc; k++) {
                float s = row[k];
                if (s > mn) { insert_top8(ts, ti, s, n0 + k); mn = ts[TOPK - 1]; }
            }
        }
        // no barrier needed: next iteration's sync A orders scan before sm rewrite
    }

    if (tid < QT) {
        int q = qBase + tid;
        size_t base = ((size_t)q * NCHUNKS + blockIdx.x) * TOPK;
        #pragma unroll
        for (int j = 0; j < TOPK; j++) { g_cs[base + j] = ts[j]; g_ci[base + j] = ti[j]; }
    }
}

// ---------------- merge per-chunk candidates + gather values ----------------
__global__ void merge_gather_kernel(const float* __restrict__ values,
                                    float* __restrict__ out) {
    const int q = blockIdx.x;
    const int tid = threadIdx.x;
    const int TOT = NCHUNKS * TOPK;    // 592
    __shared__ float cs[NCHUNKS * TOPK];
    __shared__ int   ci[NCHUNKS * TOPK];
    __shared__ int   sel[TOPK];

    for (int i = tid; i < TOT; i += 256) {
        cs[i] = g_cs[(size_t)q * TOT + i];
        ci[i] = g_ci[(size_t)q * TOT + i];
    }
    __syncthreads();

    if (tid < 32) {
        for (int r = 0; r < TOPK; r++) {
            float bs = -CUDART_INF_F; int bi = 0x7fffffff; int bj = 0;
            for (int i = tid; i < TOT; i += 32) {
                float s = cs[i]; int ix = ci[i];
                if (s > bs || (s == bs && ix < bi)) { bs = s; bi = ix; bj = i; }
            }
            #pragma unroll
            for (int off = 16; off; off >>= 1) {
                float os = __shfl_xor_sync(0xffffffff, bs, off);
                int   oi = __shfl_xor_sync(0xffffffff, bi, off);
                int   oj = __shfl_xor_sync(0xffffffff, bj, off);
                if (os > bs || (os == bs && oi < bi)) { bs = os; bi = oi; bj = oj; }
            }
            if (tid == 0) { sel[r] = bi; cs[bj] = -CUDART_INF_F; }
            __syncwarp();
        }
    }
    __syncthreads();

    for (int i = tid; i < TOPK * DD; i += 256) {
        int r = i >> 7, d = i & 127;
        out[((size_t)q * TOPK + r) * DD + d] = values[(size_t)sel[r] * DD + d];
    }
}

// ---------------- launch ----------------
extern "C" void kernel_launch(void* const* d_in, const int* in_sizes, int n_in,
                              void* d_out, int out_size) {
    const float* q_emb = (const float*)d_in[0];
    const float* keys  = (const float*)d_in[1];
    const float* vals  = (const float*)d_in[2];
    float* out = (float*)d_out;

    int B = in_sizes[0] / DD;        // 1024
    int N = in_sizes[1] / DD;        // 500000
    int CH = (N + NCHUNKS - 1) / NCHUNKS;

    normq_kernel<<<B, 128>>>(q_emb);
    rnormk_kernel<<<(N + 7) / 8, 256>>>(keys, N);

    cudaFuncSetAttribute(simtopk_kernel,
                         cudaFuncAttributeMaxDynamicSharedMemorySize, SMEM_BYTES);
    dim3 grid(NCHUNKS, B / QT);
    simtopk_kernel<<<grid, 256, SMEM_BYTES>>>(keys, N, CH);

    merge_gather_kernel<<<B, 256>>>(vals, out);
}

// round 12
// speedup vs baseline: 2.9472x; 2.9439x over previous
#include <cuda_runtime.h>
#include <cuda_bf16.h>
#include <math_constants.h>
#include <cstdint>

// ---------------- problem constants ----------------
#define BQ      1024
#define DD      128
#define TOPK    8
#define NCHUNKS 74
#define QT      128        // queries per CTA (M)
#define NT      128        // keys per tile (N)
#define NMAX    500224

// ---------------- base-target PTX helpers (NO tcgen05 / no 'a' features) ----------------
__device__ __forceinline__ uint32_t smem_to_u32(const void* p) {
    uint32_t a;
    asm("{ .reg .u64 t; cvta.to.shared.u64 t, %1; cvt.u32.u64 %0, t; }" : "=r"(a) : "l"(p));
    return a;
}

#define LDSM_X4(r, addr) \
    asm volatile("ldmatrix.sync.aligned.m8n8.x4.shared.b16 {%0,%1,%2,%3}, [%4];" \
        : "=r"((r)[0]), "=r"((r)[1]), "=r"((r)[2]), "=r"((r)[3]) : "r"(addr))

#define MMA16816(d, a, b0, b1) \
    asm volatile("mma.sync.aligned.m16n8k16.row.col.f32.bf16.bf16.f32 " \
        "{%0,%1,%2,%3}, {%4,%5,%6,%7}, {%8,%9}, {%0,%1,%2,%3};" \
        : "+f"((d)[0]), "+f"((d)[1]), "+f"((d)[2]), "+f"((d)[3]) \
        : "r"((a)[0]), "r"((a)[1]), "r"((a)[2]), "r"((a)[3]), "r"(b0), "r"(b1))

#define CP_ASYNC16(dst, src) \
    asm volatile("cp.async.cg.shared.global [%0], [%1], 16;" :: "r"(dst), "l"(src) : "memory")
#define CP_COMMIT()  asm volatile("cp.async.commit_group;" ::: "memory")
#define CP_WAIT1()   asm volatile("cp.async.wait_group 1;" ::: "memory")

// ---------------- device scratch ----------------
__device__ float          g_qn[BQ * DD];            // fp32 normalized queries (rescore)
__device__ __nv_bfloat16  g_qb[BQ * DD];            // bf16 normalized queries (MMA A)
__device__ float          g_rk[NMAX];               // 1/||k||
__device__ __nv_bfloat16  g_kb[(size_t)NMAX * DD];  // bf16 normalized keys (MMA B)
__device__ float          g_cs[BQ * NCHUNKS * 16];  // bf16-level candidates (16/(q,chunk))
__device__ int            g_ci[BQ * NCHUNKS * 16];

// ---------------- prep kernels ----------------
__global__ void normq_kernel(const float* __restrict__ q) {
    int b = blockIdx.x, t = threadIdx.x;
    float v = q[b * DD + t];
    float s = v * v;
    #pragma unroll
    for (int off = 16; off; off >>= 1) s += __shfl_xor_sync(0xffffffff, s, off);
    __shared__ float ws[4];
    if ((t & 31) == 0) ws[t >> 5] = s;
    __syncthreads();
    float inv = 1.0f / fmaxf(sqrtf(ws[0] + ws[1] + ws[2] + ws[3]), 1e-12f);
    float nv = v * inv;
    g_qn[b * DD + t] = nv;
    g_qb[b * DD + t] = __float2bfloat16(nv);
}

__global__ void prepk_kernel(const float* __restrict__ keys, int N) {
    int w = (blockIdx.x * blockDim.x + threadIdx.x) >> 5;
    int lane = threadIdx.x & 31;
    if (w >= N) return;
    float4 v = *(const float4*)(keys + (size_t)w * DD + lane * 4);
    float s = v.x * v.x + v.y * v.y + v.z * v.z + v.w * v.w;
    #pragma unroll
    for (int off = 16; off; off >>= 1) s += __shfl_xor_sync(0xffffffff, s, off);
    float r = 1.0f / fmaxf(sqrtf(s), 1e-12f);
    if (lane == 0) g_rk[w] = r;
    __nv_bfloat162 p0 = {__float2bfloat16(v.x * r), __float2bfloat16(v.y * r)};
    __nv_bfloat162 p1 = {__float2bfloat16(v.z * r), __float2bfloat16(v.w * r)};
    uint2 pk = make_uint2(*(uint32_t*)&p0, *(uint32_t*)&p1);
    *(uint2*)(g_kb + (size_t)w * DD + lane * 4) = pk;
}

// top-8 sorted-descending branch-free insert
__device__ __forceinline__ void insert_top8(float (&ts)[TOPK], int (&ti)[TOPK],
                                            float s, int id) {
    #pragma unroll
    for (int j = TOPK - 1; j >= 1; j--) {
        if (ts[j] < s) {
            bool here = ts[j - 1] >= s;
            ts[j] = here ? s : ts[j - 1];
            ti[j] = here ? id : ti[j - 1];
        }
    }
    if (ts[0] < s) { ts[0] = s; ti[0] = id; }
}

// ---------------- fused HMMA sim + per-chunk top-8 ----------------
// grid (8 qtiles, 74 chunks) [x-fastest -> qtiles of same chunk concurrent, L2 reuse]
// block 256 = 8 warps, layout 4(M) x 2(N); warp tile 32q x 64k, K=128
#define APITCH  272                 // 256B row + 16B skew (conflict-free ldmatrix)
#define ATILE   (128 * APITCH)      // 34816 B
#define B_OFF   ATILE
#define SMEM_TOTAL (3 * ATILE)      // A + 2 B buffers = 104448 B

__global__ void __launch_bounds__(256, 1)
simtopk_kernel(int N, int CH) {
    extern __shared__ char sm[];
    const uint32_t smem_base = smem_to_u32(sm);
    const int tid = threadIdx.x, wid = tid >> 5, lane = tid & 31;
    const int warp_m = wid & 3, warp_n = wid >> 2;
    const int qBase = blockIdx.x * QT;
    const int chunk = blockIdx.y;
    const int c0 = chunk * CH;
    const int c1 = min(c0 + CH, N);
    const int T = (c1 - c0 + NT - 1) / NT;

    // ---- load A (query tile, row-major bf16, pitch 272) ----
    for (int i = tid; i < 2048; i += 256) {
        int row = i >> 4, c = i & 15;
        uint4 v = *(const uint4*)(g_qb + (size_t)(qBase + row) * DD + c * 8);
        *(uint4*)(sm + row * APITCH + c * 16) = v;
    }

    // ---- prefetch B tile 0 ----
    {
        long n0 = c0;
        uint32_t bdst = smem_base + B_OFF;
        #pragma unroll
        for (int u = 0; u < 8; u++) {
            int i = tid + u * 256;
            int row = i >> 4, c = i & 15;
            const void* src = g_kb + (n0 + row) * (long)DD + c * 8;
            CP_ASYNC16(bdst + row * APITCH + c * 16, src);
        }
    }
    CP_COMMIT();
    __syncthreads();   // A visible to all

    // per-thread top-8 for each of this thread's 4 query rows
    float ts[4][TOPK];
    int   ti[4][TOPK];
    #pragma unroll
    for (int r = 0; r < 4; r++)
        #pragma unroll
        for (int j = 0; j < TOPK; j++) { ts[r][j] = -CUDART_INF_F; ti[r][j] = 0; }

    const uint32_t a_sm = smem_base;

    for (int t = 0; t < T; t++) {
        // prefetch tile t+1 into the other buffer
        if (t + 1 < T) {
            long n0n = (long)c0 + (long)(t + 1) * NT;
            uint32_t bdst = smem_base + B_OFF + ((t + 1) & 1) * ATILE;
            #pragma unroll
            for (int u = 0; u < 8; u++) {
                int i = tid + u * 256;
                int row = i >> 4, c = i & 15;
                const void* src = g_kb + (n0n + row) * (long)DD + c * 8;
                CP_ASYNC16(bdst + row * APITCH + c * 16, src);
            }
        }
        CP_COMMIT();
        CP_WAIT1();        // tile t complete (<=1 group pending)
        __syncthreads();

        const uint32_t b_sm = smem_base + B_OFF + (t & 1) * ATILE;
        const int n0 = c0 + t * NT;

        float acc[2][8][4];
        #pragma unroll
        for (int mb = 0; mb < 2; mb++)
            #pragma unroll
            for (int nb = 0; nb < 8; nb++)
                #pragma unroll
                for (int e = 0; e < 4; e++) acc[mb][nb][e] = 0.f;

        #pragma unroll
        for (int ks = 0; ks < 8; ks++) {
            uint32_t afr[2][4];
            #pragma unroll
            for (int mb = 0; mb < 2; mb++) {
                uint32_t addr = a_sm + (uint32_t)((warp_m * 32 + mb * 16 + (lane & 15)) * APITCH
                                                  + ks * 32 + ((lane >> 4) << 4));
                LDSM_X4(afr[mb], addr);
            }
            uint32_t bfr[4][4];
            #pragma unroll
            for (int p = 0; p < 4; p++) {
                uint32_t addr = b_sm + (uint32_t)((warp_n * 64 + p * 16 + ((lane >> 4) << 3)
                                                   + (lane & 7)) * APITCH
                                                  + ks * 32 + (((lane >> 3) & 1) << 4));
                LDSM_X4(bfr[p], addr);
            }
            #pragma unroll
            for (int mb = 0; mb < 2; mb++)
                #pragma unroll
                for (int p = 0; p < 4; p++) {
                    MMA16816(acc[mb][2 * p],     afr[mb], bfr[p][0], bfr[p][1]);
                    MMA16816(acc[mb][2 * p + 1], afr[mb], bfr[p][2], bfr[p][3]);
                }
        }

        // ---- in-register top-8 scan of this tile's sims ----
        #pragma unroll
        for (int mb = 0; mb < 2; mb++)
            #pragma unroll
            for (int h = 0; h < 2; h++) {
                const int r = mb * 2 + h;
                #pragma unroll
                for (int nb = 0; nb < 8; nb++)
                    #pragma unroll
                    for (int j = 0; j < 2; j++) {
                        float v = acc[mb][nb][h * 2 + j];
                        int idx = n0 + warp_n * 64 + nb * 8 + (lane & 3) * 2 + j;
                        if (v > ts[r][TOPK - 1] && idx < c1)
                            insert_top8(ts[r], ti[r], v, idx);
                    }
            }
        __syncthreads();   // all reads of buf done before it is overwritten 2 tiles later
    }

    // ---- quad merge (4 col-threads per query row) + candidate writeout ----
    #pragma unroll
    for (int r = 0; r < 4; r++) {
        float bs[TOPK]; int bi[TOPK];
        #pragma unroll
        for (int j = 0; j < TOPK; j++) { bs[j] = ts[r][j]; bi[j] = ti[r][j]; }
        #pragma unroll
        for (int srcq = 1; srcq < 4; srcq++) {
            #pragma unroll
            for (int j = 0; j < TOPK; j++) {
                float sv = __shfl_sync(0xffffffff, ts[r][j], (lane & ~3) + srcq);
                int   si = __shfl_sync(0xffffffff, ti[r][j], (lane & ~3) + srcq);
                if (sv > bs[TOPK - 1]) insert_top8(bs, bi, sv, si);
            }
        }
        if ((lane & 3) == 0) {
            int row_local = (r >> 1) * 16 + (r & 1) * 8 + (lane >> 2);
            int q = qBase + warp_m * 32 + row_local;
            size_t base = ((size_t)q * NCHUNKS + chunk) * 16 + warp_n * 8;
            #pragma unroll
            for (int j = 0; j < TOPK; j++) { g_cs[base + j] = bs[j]; g_ci[base + j] = bi[j]; }
        }
    }
}

// ---------------- merge: bf16 top-16 -> exact fp32 rescore -> top-8 + gather ----------------
__global__ void merge_gather_kernel(const float* __restrict__ keys,
                                    const float* __restrict__ values,
                                    float* __restrict__ out) {
    const int q = blockIdx.x, tid = threadIdx.x, lane = tid & 31, wid = tid >> 5;
    const int TOT = NCHUNKS * 16;     // 1184
    __shared__ float cs[NCHUNKS * 16];
    __shared__ int   ci[NCHUNKS * 16];
    __shared__ int   sel[16];
    __shared__ float ex[16];
    __shared__ int   sel8[TOPK];

    for (int i = tid; i < TOT; i += 256) {
        cs[i] = g_cs[(size_t)q * TOT + i];
        ci[i] = g_ci[(size_t)q * TOT + i];
    }
    __syncthreads();

    if (wid == 0) {
        for (int r = 0; r < 16; r++) {
            float bs = -CUDART_INF_F; int bi = 0x7fffffff; int bj = 0;
            for (int i = lane; i < TOT; i += 32) {
                float s = cs[i]; int ix = ci[i];
                if (s > bs || (s == bs && ix < bi)) { bs = s; bi = ix; bj = i; }
            }
            #pragma unroll
            for (int off = 16; off; off >>= 1) {
                float os = __shfl_xor_sync(0xffffffff, bs, off);
                int   oi = __shfl_xor_sync(0xffffffff, bi, off);
                int   oj = __shfl_xor_sync(0xffffffff, bj, off);
                if (os > bs || (os == bs && oi < bi)) { bs = os; bi = oi; bj = oj; }
            }
            if (lane == 0) { sel[r] = bi; cs[bj] = -CUDART_INF_F; }
            __syncwarp();
        }
    }
    __syncthreads();

    // exact fp32 rescore of 16 candidates: (qn . k) * rk  (round-1 formula)
    for (int c = wid; c < 16; c += 8) {
        int idx = sel[c];
        float4 kv = *(const float4*)(keys + (size_t)idx * DD + lane * 4);
        float4 qv = *(const float4*)(g_qn + (size_t)q * DD + lane * 4);
        float s = kv.x * qv.x + kv.y * qv.y + kv.z * qv.z + kv.w * qv.w;
        #pragma unroll
        for (int off = 16; off; off >>= 1) s += __shfl_xor_sync(0xffffffff, s, off);
        if (lane == 0) ex[c] = s * g_rk[idx];
    }
    __syncthreads();

    if (tid == 0) {
        bool used[16];
        #pragma unroll
        for (int i = 0; i < 16; i++) used[i] = false;
        for (int r = 0; r < TOPK; r++) {
            float bs = -CUDART_INF_F; int bi = 0x7fffffff; int bj = 0;
            for (int i = 0; i < 16; i++) {
                if (used[i]) continue;
                float s = ex[i]; int ix = sel[i];
                if (s > bs || (s == bs && ix < bi)) { bs = s; bi = ix; bj = i; }
            }
            used[bj] = true; sel8[r] = bi;
        }
    }
    __syncthreads();

    for (int i = tid; i < TOPK * DD; i += 256) {
        int r = i >> 7, d = i & 127;
        out[((size_t)q * TOPK + r) * DD + d] = values[(size_t)sel8[r] * DD + d];
    }
}

// ---------------- launch ----------------
extern "C" void kernel_launch(void* const* d_in, const int* in_sizes, int n_in,
                              void* d_out, int out_size) {
    const float* q_emb = (const float*)d_in[0];
    const float* keys  = (const float*)d_in[1];
    const float* vals  = (const float*)d_in[2];
    float* out = (float*)d_out;

    int B = in_sizes[0] / DD;       // 1024
    int N = in_sizes[1] / DD;       // 500000
    int CH = (N + NCHUNKS - 1) / NCHUNKS;

    normq_kernel<<<B, 128>>>(q_emb);
    prepk_kernel<<<(N + 7) / 8, 256>>>(keys, N);

    cudaFuncSetAttribute(simtopk_kernel,
                         cudaFuncAttributeMaxDynamicSharedMemorySize, SMEM_TOTAL);
    dim3 grid(B / QT, NCHUNKS);
    simtopk_kernel<<<grid, 256, SMEM_TOTAL>>>(N, CH);

    merge_gather_kernel<<<B, 256>>>(keys, vals, out);
}